// round 6
// baseline (speedup 1.0000x reference)
#include <cuda_runtime.h>
#include <math.h>
#include <float.h>

#define TT 256
#define BB 32
#define CC 64
#define BEAM 16
#define TOPK 4
#define NEGV (-1e9f)

typedef unsigned long long u64;

__device__ float g_lp[TT * BB * CC];

__device__ __forceinline__ float laexp(float a, float b) {
    return fmaxf(a, b) + log1pf(expf(-fabsf(a - b)));
}
__device__ __forceinline__ unsigned f2ord(float v) {
    unsigned u = __float_as_uint(v);
    return u ^ (unsigned)(((int)u >> 31) | 0x80000000);
}
__device__ __forceinline__ float ord2f(unsigned o) {
    unsigned u = (o & 0x80000000u) ? (o ^ 0x80000000u) : ~o;
    return __uint_as_float(u);
}

// ---------------------------------------------------------------------------
__global__ void logsoftmax_kernel(const float* __restrict__ data) {
    int row  = blockIdx.x * 8 + (threadIdx.x >> 5);
    int lane = threadIdx.x & 31;
    if (row >= TT * BB) return;
    const float* x = data + row * CC;
    float v0 = x[lane], v1 = x[lane + 32];
    float m = fmaxf(v0, v1);
    #pragma unroll
    for (int o = 16; o; o >>= 1) m = fmaxf(m, __shfl_xor_sync(0xffffffffu, m, o));
    float s = expf(v0 - m) + expf(v1 - m);
    #pragma unroll
    for (int o = 16; o; o >>= 1) s += __shfl_xor_sync(0xffffffffu, s, o);
    float ls = logf(s);
    g_lp[row * CC + lane]      = (v0 - m) - ls;
    g_lp[row * CC + lane + 32] = (v1 - m) - ls;
}

// ---------------------------------------------------------------------------
// One warp per batch element.
// ---------------------------------------------------------------------------
__global__ __launch_bounds__(32) void ctc_beam_kernel(
    const int* __restrict__ dlen, float* __restrict__ out)
{
    __shared__ float p_b[BEAM], p_nb[BEAM], tot[BEAM];
    __shared__ float stay_pb[BEAM], stay_pnb[BEAM];
    __shared__ u64   hcomb[BEAM], pphash[BEAM], cmask[BEAM];
    __shared__ int   lens[BEAM], lastc[BEAM], curn[BEAM];
    __shared__ float lp_s[CC];
    __shared__ float selv[BEAM];
    __shared__ int   seli[BEAM];
    __shared__ u64   surv[BEAM + BEAM * CC];   // survivor keys
    __shared__ int   nodes[TT * BEAM];
    __shared__ int   order_s[TOPK];

    const unsigned FULL = 0xffffffffu;
    int b = blockIdx.x;
    int lane = threadIdx.x;

    if (lane < BEAM) {
        float pb = (lane == 0) ? 0.0f : NEGV;
        p_b[lane] = pb; p_nb[lane] = NEGV; tot[lane] = laexp(pb, NEGV);
        hcomb[lane] = 0ull; pphash[lane] = 0ull; cmask[lane] = 0ull;
        lens[lane] = 0; lastc[lane] = -1; curn[lane] = -1;
    }
    unsigned actm = 1u;
    int length = dlen[b]; if (length > TT) length = TT;

    float lpr0 = g_lp[b * CC + lane];
    float lpr1 = g_lp[b * CC + lane + 32];
    __syncwarp();

    for (int t = 0; t < length; ++t) {
        lp_s[lane] = lpr0; lp_s[lane + 32] = lpr1;
        __syncwarp();

        // ==== phase A: merge+stays (lanes 0-15) | cmask (lanes 16-31) ========
        float stv = 0.0f;
        if (lane < BEAM) {
            int j = lane;
            int aj = (actm >> j) & 1;
            int lenj = lens[j];
            int lj = lastc[j];
            int ljs = lj < 0 ? 0 : lj;
            u64 pp = pphash[j];
            float spb  = tot[j] + lp_s[0];
            float spnb = (lenj > 0) ? (p_nb[j] + lp_s[ljs]) : NEGV;
            bool validj = aj && (lenj > 0);
            float mx = NEGV; int cnt = 0;
            if (validj) {
                float lplj = lp_s[ljs];
                #pragma unroll
                for (int i = 0; i < BEAM; ++i) {
                    if (hcomb[i] == pp) {
                        cnt++;
                        float ev = NEGV;
                        if ((actm >> i) & 1)
                            ev = ((lj == lastc[i]) ? p_b[i] : tot[i]) + lplj;
                        mx = fmaxf(mx, ev);
                    }
                }
            }
            float s = 0.0f;
            if (validj && cnt) {
                float lplj = lp_s[ljs];
                #pragma unroll
                for (int i = 0; i < BEAM; ++i) {
                    if (hcomb[i] == pp) {
                        float ev = NEGV;
                        if ((actm >> i) & 1)
                            ev = ((lj == lastc[i]) ? p_b[i] : tot[i]) + lplj;
                        s += expf(ev - mx);
                    }
                }
            }
            s += (float)(1024 - cnt) * expf(NEGV - mx);
            float merged = mx + logf(s);
            spnb = laexp(spnb, merged);
            stay_pb[j] = spb; stay_pnb[j] = spnb;
            stv = laexp(spb, spnb);
        } else {
            int i = lane - BEAM;
            u64 hci = hcomb[i];
            u64 cm = 0ull;
            #pragma unroll
            for (int j = 0; j < BEAM; ++j) {
                bool ok = ((actm >> j) & 1) && (lens[j] > 0) && (pphash[j] == hci);
                if (ok) cm |= 1ull << lastc[j];
            }
            cmask[i] = cm;
        }
        __syncwarp();

        // ==== T0 = min stay_tot (pruning threshold) ==========================
        unsigned t0o = (lane < BEAM) ? f2ord(stv) : 0xffffffffu;
        t0o = __reduce_min_sync(FULL, t0o);
        float T0 = ord2f(t0o);

        // ==== phase B: append survivors (stays + extends > T0) ===============
        if (lane < BEAM)
            surv[lane] = ((u64)f2ord(stv) << 32)
                       | ((u64)(unsigned)(2047 - lane) << 12) | (unsigned)lane;
        int cnt = BEAM;
        #pragma unroll 1
        for (int i = 0; i < BEAM; ++i) {
            bool acti = (actm >> i) & 1;
            float ti = tot[i], pbi = p_b[i];
            int li = lastc[i];
            u64 cm = cmask[i];
            float v0 = ((lane == li) ? pbi : ti) + lpr0;
            float v1 = ((lane + 32 == li) ? pbi : ti) + lpr1;
            bool k0 = acti && (lane != 0) && !((cm >> lane) & 1ull) && (v0 > T0);
            bool k1 = acti && !((cm >> (lane + 32)) & 1ull) && (v1 > T0);
            unsigned b0 = __ballot_sync(FULL, k0);
            if (k0) {
                int pos = cnt + __popc(b0 & ((1u << lane) - 1));
                int e = BEAM + i * CC + lane;
                surv[pos] = ((u64)f2ord(v0) << 32)
                          | ((u64)(unsigned)(2047 - e) << 12) | (unsigned)pos;
            }
            cnt += __popc(b0);
            unsigned b1 = __ballot_sync(FULL, k1);
            if (k1) {
                int pos = cnt + __popc(b1 & ((1u << lane) - 1));
                int e = BEAM + i * CC + 32 + lane;
                surv[pos] = ((u64)f2ord(v1) << 32)
                          | ((u64)(unsigned)(2047 - e) << 12) | (unsigned)pos;
            }
            cnt += __popc(b1);
        }
        int S = cnt;               // uniform across warp
        __syncwarp();

        // prefetch next lp row
        float lpn0, lpn1;
        {
            int nr = t + 1; if (nr > TT - 1) nr = TT - 1;
            lpn0 = g_lp[(nr * BB + b) * CC + lane];
            lpn1 = g_lp[(nr * BB + b) * CC + lane + 32];
        }

        // ==== phase C: top-16 of S survivors =================================
        u64 r0 = (lane       < S) ? surv[lane]       : 0ull;
        u64 r1 = (lane + 32  < S) ? surv[lane + 32]  : 0ull;
        u64 r2 = (lane + 64  < S) ? surv[lane + 64]  : 0ull;
        u64 r3 = (lane + 96  < S) ? surv[lane + 96]  : 0ull;
        bool tailS = (S > 128);
        u64 lk = r0;
        if (r1 > lk) lk = r1;
        if (r2 > lk) lk = r2;
        if (r3 > lk) lk = r3;
        if (tailS) {
            for (int s = 128 + lane; s < S; s += 32) {
                u64 v = surv[s];
                if (v > lk) lk = v;
            }
        }

        #pragma unroll 1
        for (int k = 0; k < BEAM; ++k) {
            unsigned up = (unsigned)(lk >> 32);
            unsigned um = __reduce_max_sync(FULL, up);
            bool hit = (up == um);
            unsigned bal = __ballot_sync(FULL, hit);
            if (__popc(bal) > 1) {
                unsigned lo = hit ? (unsigned)lk : 0u;
                unsigned lw = __reduce_max_sync(FULL, lo);
                bal = __ballot_sync(FULL, hit && ((unsigned)lk == lw));
            }
            int wl = __ffs((int)bal) - 1;
            if (lane == wl) {
                unsigned wlo = (unsigned)lk;
                seli[k] = 2047 - (int)((wlo >> 12) & 0x7ffu);
                selv[k] = ord2f((unsigned)(lk >> 32));
                int slot = (int)(wlo & 0xfffu);
                if (slot < 128) {
                    int q = slot >> 5;
                    if      (q == 0) r0 = 0ull;
                    else if (q == 1) r1 = 0ull;
                    else if (q == 2) r2 = 0ull;
                    else             r3 = 0ull;
                } else {
                    surv[slot] = 0ull;
                }
                u64 nl = r0;
                if (r1 > nl) nl = r1;
                if (r2 > nl) nl = r2;
                if (r3 > nl) nl = r3;
                if (tailS) {
                    for (int s = 128 + lane; s < S; s += 32) {
                        u64 v = surv[s];
                        if (v > nl) nl = v;
                    }
                }
                lk = nl;
            }
        }
        __syncwarp();

        // ==== phase D: commit new beam state =================================
        float npb = 0.f, npnb = 0.f; u64 nh = 0ull, npp = 0ull;
        int nlen = 0, nlast = 0, ncur = 0, nodeval = 0, nact = 0;
        bool isext = false;
        if (lane < BEAM) {
            int idx = seli[lane]; float val = selv[lane];
            bool st = idx < BEAM;
            int parent = st ? idx : ((idx - BEAM) >> 6);
            int cnew   = st ? 0   : ((idx - BEAM) & 63);
            npb  = st ? stay_pb[parent]  : NEGV;
            npnb = st ? stay_pnb[parent] : val;
            u64 hp = hcomb[parent];
            unsigned ph1 = (unsigned)(hp >> 32), ph2 = (unsigned)hp;
            unsigned cc1 = (unsigned)cnew + 1u;
            nh  = st ? hp : (((u64)(ph1 * 1000003u + cc1) << 32) | (ph2 * 69069u + cc1));
            npp = st ? pphash[parent] : hp;
            nlen  = lens[parent] + (st ? 0 : 1);
            nlast = st ? lastc[parent] : cnew;
            int pcur = curn[parent];
            ncur  = st ? pcur : (t * BEAM + lane);
            isext = !st;
            nodeval = ((pcur + 1) << 6) | cnew;
            nact = (val > -5e8f) ? 1 : 0;
        }
        __syncwarp();
        if (lane < BEAM) {
            p_b[lane] = npb; p_nb[lane] = npnb; tot[lane] = laexp(npb, npnb);
            hcomb[lane] = nh; pphash[lane] = npp;
            lens[lane] = nlen; lastc[lane] = nlast; curn[lane] = ncur;
            if (isext) nodes[t * BEAM + lane] = nodeval;
        }
        actm = __ballot_sync(FULL, nact) & 0xffffu;
        lpr0 = lpn0; lpr1 = lpn1;
        __syncwarp();
    }

    // ==== final top-4 + outputs ==============================================
    for (int e = lane; e < TOPK * TT; e += 32)
        out[2 * BB * TOPK + b * TOPK * TT + e] = -1.0f;
    __syncwarp();

    if (lane == 0) {
        unsigned used = 0u;
        for (int k = 0; k < TOPK; ++k) {
            float bv = -FLT_MAX; int bi = 0;
            for (int i = 0; i < BEAM; ++i) {
                if ((used >> i) & 1u) continue;
                if (tot[i] > bv) { bv = tot[i]; bi = i; }
            }
            used |= 1u << bi;
            order_s[k] = bi;
            out[b * TOPK + k]             = -bv;
            out[BB * TOPK + b * TOPK + k] = (float)lens[bi];
        }
    }
    __syncwarp();

    if (lane < TOPK) {
        int bm = order_s[lane];
        int id = curn[bm];
        float* lbl = out + 2 * BB * TOPK + (b * TOPK + lane) * TT;
        for (int pos = lens[bm] - 1; pos >= 0; --pos) {
            int pk = nodes[id];
            lbl[pos] = (float)(pk & 63);
            id = (pk >> 6) - 1;
        }
    }
}

extern "C" void kernel_launch(void* const* d_in, const int* in_sizes, int n_in,
                              void* d_out, int out_size)
{
    const float* data = (const float*)d_in[0];
    const int*   dlen = (const int*)d_in[1];
    float*       out  = (float*)d_out;

    logsoftmax_kernel<<<(TT * BB) / 8, 256>>>(data);
    ctc_beam_kernel<<<BB, 32>>>(dlen, out);
}

// round 9
// speedup vs baseline: 1.3601x; 1.3601x over previous
#include <cuda_runtime.h>
#include <math.h>
#include <float.h>

#define TT 256
#define BB 32
#define CC 64
#define BEAM 16
#define TOPK 4
#define NEGV (-1e9f)

typedef unsigned long long u64;

__device__ float g_lp[TT * BB * CC];

__device__ __forceinline__ float laexp(float a, float b) {
    return fmaxf(a, b) + log1pf(expf(-fabsf(a - b)));
}
__device__ __forceinline__ unsigned f2ord(float v) {
    unsigned u = __float_as_uint(v);
    return u ^ (unsigned)(((int)u >> 31) | 0x80000000);
}
__device__ __forceinline__ float ord2f(unsigned o) {
    unsigned u = (o & 0x80000000u) ? (o ^ 0x80000000u) : ~o;
    return __uint_as_float(u);
}

// ---------------------------------------------------------------------------
__global__ void logsoftmax_kernel(const float* __restrict__ data) {
    int row  = blockIdx.x * 8 + (threadIdx.x >> 5);
    int lane = threadIdx.x & 31;
    if (row >= TT * BB) return;
    const float* x = data + row * CC;
    float v0 = x[lane], v1 = x[lane + 32];
    float m = fmaxf(v0, v1);
    #pragma unroll
    for (int o = 16; o; o >>= 1) m = fmaxf(m, __shfl_xor_sync(0xffffffffu, m, o));
    float s = expf(v0 - m) + expf(v1 - m);
    #pragma unroll
    for (int o = 16; o; o >>= 1) s += __shfl_xor_sync(0xffffffffu, s, o);
    float ls = logf(s);
    g_lp[row * CC + lane]      = (v0 - m) - ls;
    g_lp[row * CC + lane + 32] = (v1 - m) - ls;
}

#define INSERTC(KEY) do { u64 _k = (KEY);                                  \
    if (_k > c2) {                                                         \
        if (_k > c0) { c2 = c1; c1 = c0; c0 = _k; }                        \
        else if (_k > c1) { c2 = c1; c1 = _k; }                            \
        else c2 = _k;                                                      \
    } } while (0)

// ---------------------------------------------------------------------------
// One warp per batch element.
// ---------------------------------------------------------------------------
__global__ __launch_bounds__(32) void ctc_beam_kernel(
    const int* __restrict__ dlen, float* __restrict__ out)
{
    __shared__ float p_b[BEAM], p_nb[BEAM], tot[BEAM];
    __shared__ float stay_pb[BEAM], stay_pnb[BEAM];
    __shared__ u64   hcomb[BEAM], pphash[BEAM], cmask_s[BEAM];
    __shared__ int   lens[BEAM], lastc[BEAM], curn[BEAM];
    __shared__ float4 rec[BEAM];      // (tot, p_b, lastc-as-float, 0)
    __shared__ float lp_s[CC];
    __shared__ float selv[BEAM];
    __shared__ int   seli[BEAM];
    __shared__ int   nodes[TT * BEAM];
    __shared__ int   order_s[TOPK];

    const unsigned FULL = 0xffffffffu;
    int b = blockIdx.x;
    int lane = threadIdx.x;

    if (lane < BEAM) {
        float pb = (lane == 0) ? 0.0f : NEGV;
        p_b[lane] = pb; p_nb[lane] = NEGV; tot[lane] = laexp(pb, NEGV);
        hcomb[lane] = 0ull; pphash[lane] = 0ull;
        lens[lane] = 0; lastc[lane] = -1; curn[lane] = -1;
    }
    unsigned actm = 1u;
    int length = dlen[b]; if (length > TT) length = TT;

    float lpr0 = g_lp[b * CC + lane];
    float lpr1 = g_lp[b * CC + lane + 32];
    __syncwarp();

    for (int t = 0; t < length; ++t) {
        lp_s[lane] = lpr0; lp_s[lane + 32] = lpr1;
        __syncwarp();

        // ==== phase A: merge+stays+rec (lanes 0-15) | cmask (lanes 16-31) ====
        float stv = 0.0f;
        if (lane < BEAM) {
            int j = lane;
            int aj = (actm >> j) & 1;
            int lenj = lens[j];
            int lj = lastc[j];
            int ljs = lj < 0 ? 0 : lj;
            u64 pp = pphash[j];
            float tj = tot[j], pbj = p_b[j];
            rec[j] = make_float4(tj, pbj, __int_as_float(lj), 0.0f);
            float spb  = tj + lp_s[0];
            float spnb = (lenj > 0) ? (p_nb[j] + lp_s[ljs]) : NEGV;
            bool validj = aj && (lenj > 0);
            float mx = NEGV; int cnt = 0;
            if (validj) {
                float lplj = lp_s[ljs];
                #pragma unroll
                for (int i = 0; i < BEAM; ++i) {
                    if (hcomb[i] == pp) {
                        cnt++;
                        float ev = NEGV;
                        if ((actm >> i) & 1)
                            ev = ((lj == lastc[i]) ? p_b[i] : tot[i]) + lplj;
                        mx = fmaxf(mx, ev);
                    }
                }
            }
            float s = 0.0f;
            if (validj && cnt) {
                float lplj = lp_s[ljs];
                #pragma unroll
                for (int i = 0; i < BEAM; ++i) {
                    if (hcomb[i] == pp) {
                        float ev = NEGV;
                        if ((actm >> i) & 1)
                            ev = ((lj == lastc[i]) ? p_b[i] : tot[i]) + lplj;
                        s += expf(ev - mx);
                    }
                }
            }
            s += (float)(1024 - cnt) * expf(NEGV - mx);
            float merged = mx + logf(s);
            spnb = laexp(spnb, merged);
            stay_pb[j] = spb; stay_pnb[j] = spnb;
            stv = laexp(spb, spnb);
        } else {
            int i = lane - BEAM;
            u64 hci = hcomb[i];
            u64 cm = 1ull;                           // blank always masked
            #pragma unroll
            for (int j = 0; j < BEAM; ++j) {
                bool ok = ((actm >> j) & 1) && (lens[j] > 0) && (pphash[j] == hci);
                if (ok) cm |= 1ull << lastc[j];
            }
            if (!((actm >> i) & 1)) cm = ~0ull;      // inactive: mask all
            cmask_s[i] = cm;
        }
        __syncwarp();

        // ==== T0 = min stay_tot ==============================================
        unsigned t0o = (lane < BEAM) ? f2ord(stv) : 0xffffffffu;
        t0o = __reduce_min_sync(FULL, t0o);
        float T0 = ord2f(t0o);

        // ==== phase B: build pruned keys + top-3 cache (rotated mapping) =====
        u64 kk[33];
        u64 c0 = 0ull, c1 = 0ull, c2 = 0ull;
        int nsurv = 0;
        #pragma unroll
        for (int m = 0; m < 33; ++m) {
            int e = m * 32 + ((lane + m) & 31);
            u64 key = 0ull;
            if (e < BEAM) {
                key = ((u64)f2ord(stv) << 32)
                    | (u64)(unsigned)(((2047 - e) << 6) | m);
            } else if (e < BEAM + BEAM * CC) {
                int x = e - BEAM, i = x >> 6, c = x & 63;
                u64 cm = cmask_s[i];
                float4 r = rec[i];
                float base = (c == __float_as_int(r.z)) ? r.y : r.x;
                float v = base + lp_s[c];
                if (!((cm >> c) & 1ull) && (v > T0))
                    key = ((u64)f2ord(v) << 32)
                        | (u64)(unsigned)(((2047 - e) << 6) | m);
            }
            kk[m] = key;
            if (key) { nsurv++; INSERTC(key); }
        }

        // prefetch next lp row (hidden behind extraction)
        float lpn0, lpn1;
        {
            int nr = t + 1; if (nr > TT - 1) nr = TT - 1;
            lpn0 = g_lp[(nr * BB + b) * CC + lane];
            lpn1 = g_lp[(nr * BB + b) * CC + lane + 32];
        }

        // ==== phase C: top-16 via redux + per-lane cache =====================
        u64 pmask = 0ull;
        #pragma unroll 1
        for (int k = 0; k < BEAM; ++k) {
            unsigned up = (unsigned)(c0 >> 32);
            unsigned um = __reduce_max_sync(FULL, up);
            bool hit = (c0 != 0ull) && (up == um);
            unsigned bal = __ballot_sync(FULL, hit);
            if (__popc(bal) > 1) {                    // exact value tie
                unsigned lo = hit ? (unsigned)c0 : 0u;
                unsigned lw = __reduce_max_sync(FULL, lo);
                bal = __ballot_sync(FULL, hit && ((unsigned)c0 == lw));
            }
            int wl = __ffs((int)bal) - 1;
            if (lane == wl) {
                unsigned klo = (unsigned)c0;
                seli[k] = 2047 - (int)(klo >> 6);
                selv[k] = ord2f((unsigned)(c0 >> 32));
                pmask |= 1ull << (klo & 63u);
                c0 = c1; c1 = c2; c2 = 0ull;
                nsurv--;
                if (c0 == 0ull && nsurv > 0) {        // rare refill
                    #pragma unroll
                    for (int m = 0; m < 33; ++m) {
                        u64 kx = ((pmask >> m) & 1ull) ? 0ull : kk[m];
                        if (kx) INSERTC(kx);
                    }
                }
            }
        }
        __syncwarp();

        // ==== phase D: commit new beam state =================================
        float npb = 0.f, npnb = 0.f; u64 nh = 0ull, npp = 0ull;
        int nlen = 0, nlast = 0, ncur = 0, nodeval = 0, nact = 0;
        bool isext = false;
        if (lane < BEAM) {
            int idx = seli[lane]; float val = selv[lane];
            bool st = idx < BEAM;
            int parent = st ? idx : ((idx - BEAM) >> 6);
            int cnew   = st ? 0   : ((idx - BEAM) & 63);
            npb  = st ? stay_pb[parent]  : NEGV;
            npnb = st ? stay_pnb[parent] : val;
            u64 hp = hcomb[parent];
            unsigned ph1 = (unsigned)(hp >> 32), ph2 = (unsigned)hp;
            unsigned cc1 = (unsigned)cnew + 1u;
            nh  = st ? hp : (((u64)(ph1 * 1000003u + cc1) << 32) | (ph2 * 69069u + cc1));
            npp = st ? pphash[parent] : hp;
            nlen  = lens[parent] + (st ? 0 : 1);
            nlast = st ? lastc[parent] : cnew;
            int pcur = curn[parent];
            ncur  = st ? pcur : (t * BEAM + lane);
            isext = !st;
            nodeval = ((pcur + 1) << 6) | cnew;
            nact = (val > -5e8f) ? 1 : 0;
        }
        __syncwarp();
        if (lane < BEAM) {
            p_b[lane] = npb; p_nb[lane] = npnb; tot[lane] = laexp(npb, npnb);
            hcomb[lane] = nh; pphash[lane] = npp;
            lens[lane] = nlen; lastc[lane] = nlast; curn[lane] = ncur;
            if (isext) nodes[t * BEAM + lane] = nodeval;
        }
        actm = __ballot_sync(FULL, nact) & 0xffffu;
        lpr0 = lpn0; lpr1 = lpn1;
        __syncwarp();
    }

    // ==== final top-4 + outputs ==============================================
    for (int e = lane; e < TOPK * TT; e += 32)
        out[2 * BB * TOPK + b * TOPK * TT + e] = -1.0f;
    __syncwarp();

    if (lane == 0) {
        unsigned used = 0u;
        for (int k = 0; k < TOPK; ++k) {
            float bv = -FLT_MAX; int bi = 0;
            for (int i = 0; i < BEAM; ++i) {
                if ((used >> i) & 1u) continue;
                if (tot[i] > bv) { bv = tot[i]; bi = i; }
            }
            used |= 1u << bi;
            order_s[k] = bi;
            out[b * TOPK + k]             = -bv;
            out[BB * TOPK + b * TOPK + k] = (float)lens[bi];
        }
    }
    __syncwarp();

    if (lane < TOPK) {
        int bm = order_s[lane];
        int id = curn[bm];
        float* lbl = out + 2 * BB * TOPK + (b * TOPK + lane) * TT;
        for (int pos = lens[bm] - 1; pos >= 0; --pos) {
            int pk = nodes[id];
            lbl[pos] = (float)(pk & 63);
            id = (pk >> 6) - 1;
        }
    }
}

extern "C" void kernel_launch(void* const* d_in, const int* in_sizes, int n_in,
                              void* d_out, int out_size)
{
    const float* data = (const float*)d_in[0];
    const int*   dlen = (const int*)d_in[1];
    float*       out  = (float*)d_out;

    logsoftmax_kernel<<<(TT * BB) / 8, 256>>>(data);
    ctc_beam_kernel<<<BB, 32>>>(dlen, out);
}